// round 5
// baseline (speedup 1.0000x reference)
#include <cuda_runtime.h>

// ============================================================================
// BiSDA_3977139716506 — exact algebraic simplification (see R2 proof).
//
// The final LIF (tau=2, V_TH=1, v_reset=0) receives inputs in [0,1], so its
// membrane obeys v_t <= 1 - 2^-t < 1 — it can never reach threshold, and its
// spike output is EXACTLY zero for every possible input. Then pw @ 0 = 0 and
// BatchNorm(0) = beta exactly:
//
//     reference(...) == broadcast(p_beta[c]) over [T=4, B=2, C=128, 8,32,32]
//
// Verified: R1 full-compute kernel and R2 broadcast kernel both pass with
// rel_err = 0.0.
//
// This round: pure store-throughput tuning. Each thread writes 8 consecutive
// float4s (128 B = one full L2 sector-line; a warp covers 4 KB contiguous).
// Grid shrinks 8192 -> 512 blocks, eliminating multi-wave scheduling overhead
// and amortizing index math / the uniform p_beta load over 8 STG.128s.
//
// Channel mapping: element i has c = (i >> 13) & 127  (spatial = 8192 floats).
// A thread's 32 consecutive floats (base float4 idx = tid*8, aligned) never
// cross a channel boundary: c = (thread_idx >> 8) & 127, warp-uniform.
// ============================================================================

#define TOT 8388608   // total output floats

__global__ void __launch_bounds__(512) broadcast_beta_kernel(
    const float* __restrict__ p_beta, float4* __restrict__ out4)
{
    int i  = blockIdx.x * 512 + threadIdx.x;   // thread index, [0, TOT/32)
    float b = __ldg(&p_beta[(i >> 8) & 127]);  // warp-uniform channel load
    float4 v = make_float4(b, b, b, b);
    float4* p = out4 + (long)i * 8;            // 8 float4 = 128 B per thread
#pragma unroll
    for (int j = 0; j < 8; j++) p[j] = v;
}

extern "C" void kernel_launch(void* const* d_in, const int* in_sizes, int n_in,
                              void* d_out, int out_size)
{
    // metadata order: x, qw, q_gamma, q_beta, kw, k_gamma, k_beta,
    //                 v_gamma, v_beta, pw, p_gamma, p_beta
    const float* p_beta = (const float*)d_in[11];
    float4* out4 = (float4*)d_out;

    // TOT/32 = 262144 threads -> 512 blocks x 512 threads, 8x STG.128 each.
    broadcast_beta_kernel<<<512, 512>>>(p_beta, out4);
}

// round 6
// speedup vs baseline: 2.6926x; 2.6926x over previous
#include <cuda_runtime.h>

// ============================================================================
// BiSDA_3977139716506 — exact algebraic simplification (proof in R2).
//
// The final LIF (tau=2, V_TH=1, v_reset=0) receives inputs in [0,1]; its
// membrane obeys v_t <= 1 - 2^-t < 1, so it can never fire: output is exactly
// zero for all inputs. Then pw @ 0 = 0 and BatchNorm(0) = beta exactly:
//
//     reference(...) == broadcast(p_beta[c]) over [T=4, B=2, C=128, 8,32,32]
//
// Verified rel_err = 0.0 by both the full-compute kernel (R1) and broadcast
// kernels (R2, R3).
//
// R3 lesson: per-THREAD-contiguous 128-B chunks break cross-lane coalescing
// (each STG.128 touched 32 distinct lines -> 8x L1tex wavefront inflation,
// 21.5 us). This round restores lane-contiguous stores (one instruction =
// 512 contiguous bytes) and adds MLP via 4 grid-stride store partitions per
// thread: 1024 blocks x 512 threads x 4 STG.128.
//
// Channel of float4 index i4: c = (i4 >> 11) & 127 (2048 float4 per channel
// block); warp-uniform since stride 4 divides 2048.
// ============================================================================

#define N4     2097152            // total float4 stores (8388608 floats / 4)
#define STRIDE 524288             // 1024 blocks * 512 threads

__global__ void __launch_bounds__(512) broadcast_beta_kernel(
    const float* __restrict__ p_beta, float4* __restrict__ out4)
{
    int i = blockIdx.x * 512 + threadIdx.x;    // [0, STRIDE)
#pragma unroll
    for (int j = 0; j < 4; j++) {
        int i4 = i + j * STRIDE;               // lane-contiguous within warp
        float b = __ldg(&p_beta[(i4 >> 11) & 127]);
        out4[i4] = make_float4(b, b, b, b);
    }
}

extern "C" void kernel_launch(void* const* d_in, const int* in_sizes, int n_in,
                              void* d_out, int out_size)
{
    // metadata order: x, qw, q_gamma, q_beta, kw, k_gamma, k_beta,
    //                 v_gamma, v_beta, pw, p_gamma, p_beta
    const float* p_beta = (const float*)d_in[11];
    float4* out4 = (float4*)d_out;

    broadcast_beta_kernel<<<1024, 512>>>(p_beta, out4);
}